// round 1
// baseline (speedup 1.0000x reference)
#include <cuda_runtime.h>

// Problem constants
#define B_SZ 4
#define T_LEN 2048
#define C_DIM 1024
#define H_N 16
#define D_H 64
#define M_ROWS 8192   // B*T

// Scratch: Q,K,V,Y in head layout [(b*H+h)*T + t]*D + d
__device__ float g_q[M_ROWS * C_DIM];
__device__ float g_k[M_ROWS * C_DIM];
__device__ float g_v[M_ROWS * C_DIM];
__device__ float g_y[M_ROWS * C_DIM];

// ---------------------------------------------------------------------------
// GEMM: out[m,n] = sum_k A[m,k] * W[k,n] + bias[n]
// A_HEAD:  A is read from head layout (for the output projection reading g_y)
// OUT_HEAD: out is written in head layout (for Q/K/V projections)
// Tile: BM=128, BN=128, BK=8, 256 threads, 8x8 per thread.
// ---------------------------------------------------------------------------
__device__ __forceinline__ int head_idx(int m, int n) {
    // ((b*H + h)*T + t)*D + d ; T=2048, D=64, H=16
    return (((((m >> 11) << 4) + (n >> 6)) << 11 | (m & 2047)) << 6) + (n & 63);
}

template <bool A_HEAD, bool OUT_HEAD>
__global__ __launch_bounds__(256)
void gemm_kernel(const float* __restrict__ A, const float* __restrict__ W,
                 const float* __restrict__ bias, float* __restrict__ out)
{
    __shared__ float As[8][128];   // transposed A tile
    __shared__ float Bs[8][128];

    const int bm = blockIdx.y * 128;
    const int bn = blockIdx.x * 128;
    const int tid = threadIdx.x;
    const int tx = tid & 15;
    const int ty = tid >> 4;

    const int aRow = tid >> 1;           // 0..127
    const int aK4  = (tid & 1) << 2;     // 0 or 4
    const int bRow = tid >> 5;           // 0..7
    const int bC4  = (tid & 31) << 2;    // 0..124

    float acc[8][8];
#pragma unroll
    for (int i = 0; i < 8; i++)
#pragma unroll
        for (int j = 0; j < 8; j++) acc[i][j] = 0.f;

    for (int k0 = 0; k0 < C_DIM; k0 += 8) {
        const int m = bm + aRow;
        const int k = k0 + aK4;
        const float* ap;
        if (A_HEAD) ap = A + head_idx(m, k);
        else        ap = A + m * C_DIM + k;
        const float4 av = *(const float4*)ap;
        As[aK4 + 0][aRow] = av.x;
        As[aK4 + 1][aRow] = av.y;
        As[aK4 + 2][aRow] = av.z;
        As[aK4 + 3][aRow] = av.w;

        const float4 bv = *(const float4*)(W + (k0 + bRow) * C_DIM + bn + bC4);
        *(float4*)&Bs[bRow][bC4] = bv;

        __syncthreads();

#pragma unroll
        for (int kk = 0; kk < 8; kk++) {
            const float4 a0 = *(const float4*)&As[kk][ty * 8];
            const float4 a1 = *(const float4*)&As[kk][ty * 8 + 4];
            const float4 b0 = *(const float4*)&Bs[kk][tx * 8];
            const float4 b1 = *(const float4*)&Bs[kk][tx * 8 + 4];
            const float ra[8] = {a0.x, a0.y, a0.z, a0.w, a1.x, a1.y, a1.z, a1.w};
            const float rb[8] = {b0.x, b0.y, b0.z, b0.w, b1.x, b1.y, b1.z, b1.w};
#pragma unroll
            for (int i = 0; i < 8; i++)
#pragma unroll
                for (int j = 0; j < 8; j++)
                    acc[i][j] += ra[i] * rb[j];
        }
        __syncthreads();
    }

    // Epilogue with bias, vectorized stores
#pragma unroll
    for (int i = 0; i < 8; i++) {
        const int m = bm + ty * 8 + i;
#pragma unroll
        for (int jj = 0; jj < 2; jj++) {
            const int n = bn + tx * 8 + jj * 4;
            float4 v;
            v.x = acc[i][jj * 4 + 0] + bias[n + 0];
            v.y = acc[i][jj * 4 + 1] + bias[n + 1];
            v.z = acc[i][jj * 4 + 2] + bias[n + 2];
            v.w = acc[i][jj * 4 + 3] + bias[n + 3];
            float* op;
            if (OUT_HEAD) op = out + head_idx(m, n);   // n..n+3 contiguous in d
            else          op = out + m * C_DIM + n;
            *(float4*)op = v;
        }
    }
}

// ---------------------------------------------------------------------------
// Flash attention (causal), fp32. Per block: one 64-query tile of one (b,h).
// Br=Bc=64, D=64. 256 threads = 16x16, each owns 4x4 of S/P and 4x4 of O.
// Smem: Qs,Ks stride 65 (padded), Vs,Ps stride 64 (float4-friendly).
// ---------------------------------------------------------------------------
#define QK_LD 65
#define PV_LD 64
#define SM_Q 0
#define SM_K (64 * QK_LD)
#define SM_V (2 * 64 * QK_LD)
#define SM_P (2 * 64 * QK_LD + 64 * PV_LD)
#define ATTN_SMEM_FLOATS (2 * 64 * QK_LD + 2 * 64 * PV_LD)

__global__ __launch_bounds__(256)
void attn_kernel(const float* __restrict__ Q, const float* __restrict__ K,
                 const float* __restrict__ V, float* __restrict__ Y)
{
    extern __shared__ float sm[];
    float* Qs = sm + SM_Q;
    float* Ks = sm + SM_K;
    float* Vs = sm + SM_V;
    float* Ps = sm + SM_P;

    const int bh = blockIdx.y;          // 0..63
    const int qb = blockIdx.x;          // 0..31
    const int q0 = qb << 6;
    const float* Qp = Q + (((size_t)bh << 11) + q0) * 64;
    const float* Kp = K + ((size_t)bh << 11) * 64;
    const float* Vp = V + ((size_t)bh << 11) * 64;

    const int tid = threadIdx.x;
    const int tx = tid & 15;
    const int ty = tid >> 4;
    const int r0 = ty << 2;
    const int c0 = tx << 2;

    // Load Q tile: 64x64 floats
    for (int i = tid; i < 1024; i += 256) {
        const int r = i >> 4, c4 = (i & 15) << 2;
        const float4 v = *(const float4*)(Qp + (r << 6) + c4);
        float* dst = Qs + r * QK_LD + c4;
        dst[0] = v.x; dst[1] = v.y; dst[2] = v.z; dst[3] = v.w;
    }

    float o[4][4];
    float mi[4], li[4];
#pragma unroll
    for (int i = 0; i < 4; i++) {
        mi[i] = -1e30f; li[i] = 0.f;
#pragma unroll
        for (int j = 0; j < 4; j++) o[i][j] = 0.f;
    }

    for (int kt = 0; kt <= qb; kt++) {
        __syncthreads();   // previous-iteration consumers done before overwrite
        const float* kbase = Kp + (kt << 12);
        const float* vbase = Vp + (kt << 12);
        for (int i = tid; i < 1024; i += 256) {
            const int r = i >> 4, c4 = (i & 15) << 2;
            const float4 kv = *(const float4*)(kbase + (r << 6) + c4);
            float* kd = Ks + r * QK_LD + c4;
            kd[0] = kv.x; kd[1] = kv.y; kd[2] = kv.z; kd[3] = kv.w;
            const float4 vv = *(const float4*)(vbase + (r << 6) + c4);
            *(float4*)(Vs + r * PV_LD + c4) = vv;
        }
        __syncthreads();

        // S = Q K^T
        float s[4][4];
#pragma unroll
        for (int i = 0; i < 4; i++)
#pragma unroll
            for (int j = 0; j < 4; j++) s[i][j] = 0.f;

        for (int d = 0; d < 64; d++) {
            float qa[4], kb[4];
#pragma unroll
            for (int i = 0; i < 4; i++) qa[i] = Qs[(r0 + i) * QK_LD + d];
#pragma unroll
            for (int j = 0; j < 4; j++) kb[j] = Ks[(c0 + j) * QK_LD + d];
#pragma unroll
            for (int i = 0; i < 4; i++)
#pragma unroll
                for (int j = 0; j < 4; j++)
                    s[i][j] += qa[i] * kb[j];
        }

        // scale + causal mask (only the diagonal tile needs masking)
        const bool diag = (kt == qb);
#pragma unroll
        for (int i = 0; i < 4; i++)
#pragma unroll
            for (int j = 0; j < 4; j++) {
                s[i][j] *= 0.125f;
                if (diag && (c0 + j) > (r0 + i)) s[i][j] = -1e30f;
            }

        // online softmax
        float mnew[4], alpha[4];
#pragma unroll
        for (int i = 0; i < 4; i++) {
            float rm = fmaxf(fmaxf(s[i][0], s[i][1]), fmaxf(s[i][2], s[i][3]));
            rm = fmaxf(rm, __shfl_xor_sync(0xffffffffu, rm, 1, 16));
            rm = fmaxf(rm, __shfl_xor_sync(0xffffffffu, rm, 2, 16));
            rm = fmaxf(rm, __shfl_xor_sync(0xffffffffu, rm, 4, 16));
            rm = fmaxf(rm, __shfl_xor_sync(0xffffffffu, rm, 8, 16));
            mnew[i] = fmaxf(mi[i], rm);
            alpha[i] = __expf(mi[i] - mnew[i]);
        }
#pragma unroll
        for (int i = 0; i < 4; i++) {
            float4 pv;
            pv.x = __expf(s[i][0] - mnew[i]);
            pv.y = __expf(s[i][1] - mnew[i]);
            pv.z = __expf(s[i][2] - mnew[i]);
            pv.w = __expf(s[i][3] - mnew[i]);
            *(float4*)(Ps + (r0 + i) * PV_LD + c0) = pv;
            float sum = pv.x + pv.y + pv.z + pv.w;
            sum += __shfl_xor_sync(0xffffffffu, sum, 1, 16);
            sum += __shfl_xor_sync(0xffffffffu, sum, 2, 16);
            sum += __shfl_xor_sync(0xffffffffu, sum, 4, 16);
            sum += __shfl_xor_sync(0xffffffffu, sum, 8, 16);
            li[i] = li[i] * alpha[i] + sum;
            mi[i] = mnew[i];
#pragma unroll
            for (int j = 0; j < 4; j++) o[i][j] *= alpha[i];
        }
        __syncthreads();

        // O += P V
        for (int c = 0; c < 64; c++) {
            float pa[4];
#pragma unroll
            for (int i = 0; i < 4; i++) pa[i] = Ps[(r0 + i) * PV_LD + c];
            const float4 vb = *(const float4*)(Vs + c * PV_LD + c0);
#pragma unroll
            for (int i = 0; i < 4; i++) {
                o[i][0] += pa[i] * vb.x;
                o[i][1] += pa[i] * vb.y;
                o[i][2] += pa[i] * vb.z;
                o[i][3] += pa[i] * vb.w;
            }
        }
    }

    // normalize + store (head layout)
    float* yp = Y + (((size_t)bh << 11) + q0) * 64;
#pragma unroll
    for (int i = 0; i < 4; i++) {
        const float inv = 1.f / li[i];
        float4 v;
        v.x = o[i][0] * inv;
        v.y = o[i][1] * inv;
        v.z = o[i][2] * inv;
        v.w = o[i][3] * inv;
        *(float4*)(yp + (r0 + i) * 64 + c0) = v;
    }
}

// ---------------------------------------------------------------------------
extern "C" void kernel_launch(void* const* d_in, const int* in_sizes, int n_in,
                              void* d_out, int out_size)
{
    const float* x  = (const float*)d_in[0];
    const float* Wq = (const float*)d_in[1];
    const float* bq = (const float*)d_in[2];
    const float* Wk = (const float*)d_in[3];
    const float* bk = (const float*)d_in[4];
    const float* Wv = (const float*)d_in[5];
    const float* bv = (const float*)d_in[6];
    const float* Wp = (const float*)d_in[7];
    const float* bp = (const float*)d_in[8];
    float* out = (float*)d_out;

    float *q, *k, *v, *y;
    cudaGetSymbolAddress((void**)&q, g_q);
    cudaGetSymbolAddress((void**)&k, g_k);
    cudaGetSymbolAddress((void**)&v, g_v);
    cudaGetSymbolAddress((void**)&y, g_y);

    const dim3 gg(C_DIM / 128, M_ROWS / 128);   // (8, 64)
    gemm_kernel<false, true><<<gg, 256>>>(x, Wq, bq, q);
    gemm_kernel<false, true><<<gg, 256>>>(x, Wk, bk, k);
    gemm_kernel<false, true><<<gg, 256>>>(x, Wv, bv, v);

    const int attn_smem = ATTN_SMEM_FLOATS * (int)sizeof(float);  // 66048 B
    cudaFuncSetAttribute(attn_kernel, cudaFuncAttributeMaxDynamicSharedMemorySize,
                         attn_smem);
    const dim3 ga(T_LEN / 64, B_SZ * H_N);      // (32, 64)
    attn_kernel<<<ga, 256, attn_smem>>>(q, k, v, y);

    gemm_kernel<true, false><<<gg, 256>>>(y, Wp, bp, out);
}

// round 2
// speedup vs baseline: 1.6781x; 1.6781x over previous
#include <cuda_runtime.h>
#include <cstdint>

// Problem constants
#define B_SZ 4
#define T_LEN 2048
#define C_DIM 1024
#define H_N 16
#define D_H 64
#define M_ROWS 8192   // B*T

// Scratch: Q,K,V,Y in head layout [(b*H+h)*T + t]*D + d
__device__ float g_q[M_ROWS * C_DIM];
__device__ float g_k[M_ROWS * C_DIM];
__device__ float g_v[M_ROWS * C_DIM];
__device__ float g_y[M_ROWS * C_DIM];

__device__ __forceinline__ int head_idx(int m, int n) {
    // ((b*H + h)*T + t)*D + d ; T=2048, D=64, H=16
    return (((((m >> 11) << 4) + (n >> 6)) << 11 | (m & 2047)) << 6) + (n & 63);
}

__device__ __forceinline__ uint32_t f2tf32(float f) {
    uint32_t u;
    asm("cvt.rna.tf32.f32 %0, %1;" : "=r"(u) : "f"(f));
    return u;
}

#define MMA_TF32(C0,C1,C2,C3,A0,A1,A2,A3,B0,B1)                           \
    asm volatile("mma.sync.aligned.m16n8k8.row.col.f32.tf32.tf32.f32 "    \
        "{%0,%1,%2,%3},{%4,%5,%6,%7},{%8,%9},{%0,%1,%2,%3};"              \
        : "+f"(C0), "+f"(C1), "+f"(C2), "+f"(C3)                          \
        : "r"(A0), "r"(A1), "r"(A2), "r"(A3), "r"(B0), "r"(B1))

#define CP_ASYNC16(smem_u32, gptr)                                        \
    asm volatile("cp.async.ca.shared.global [%0], [%1], 16;"              \
        :: "r"(smem_u32), "l"(gptr))
#define CP_COMMIT()  asm volatile("cp.async.commit_group;")
#define CP_WAIT(N)   asm volatile("cp.async.wait_group %0;" :: "n"(N))

// ---------------------------------------------------------------------------
// TF32 tensor-core GEMM: out[m,n] = sum_k A[m,k]*W[k,n] + bias[n]
// BM=128, BN=128, BK=16; 256 threads = 8 warps (4m x 2n), warp tile 32x64.
// cp.async double-buffered. A stored [m][k] stride 20; B stored [k][n] stride 132.
// ---------------------------------------------------------------------------
#define BK 16
#define AS_LD 20
#define BS_LD 132

template <bool A_HEAD, bool OUT_HEAD>
__global__ __launch_bounds__(256)
void gemm_tf32(const float* __restrict__ A, const float* __restrict__ W,
               const float* __restrict__ bias, float* __restrict__ out)
{
    __shared__ float As[2][128 * AS_LD];
    __shared__ float Bs[2][BK * BS_LD];

    const int bm = blockIdx.y * 128;
    const int bn = blockIdx.x * 128;
    const int tid = threadIdx.x;
    const int warp = tid >> 5;
    const int lane = tid & 31;
    const int group = lane >> 2;     // 0..7
    const int tig = lane & 3;        // 0..3
    const int wm = (warp >> 1) * 32; // 0,32,64,96
    const int wn = (warp & 1) * 64;  // 0,64

    // per-thread load coordinates (2 float4 each for A and B per stage)
    const int aRow0 = tid >> 2;                 // f = tid
    const int aC40  = (tid & 3) << 2;
    const int aRow1 = (tid + 256) >> 2;
    const int aC41  = aC40;                     // (f&3) identical for f=tid+256
    const int bRow0 = tid >> 5;
    const int bC40  = (tid & 31) << 2;
    const int bRow1 = (tid + 256) >> 5;
    const int bC41  = bC40;

    const uint32_t asBase = (uint32_t)__cvta_generic_to_shared(&As[0][0]);
    const uint32_t bsBase = (uint32_t)__cvta_generic_to_shared(&Bs[0][0]);
    const uint32_t asStageBytes = 128 * AS_LD * 4;
    const uint32_t bsStageBytes = BK * BS_LD * 4;

    float acc[2][8][4];
#pragma unroll
    for (int mt = 0; mt < 2; mt++)
#pragma unroll
        for (int nt = 0; nt < 8; nt++)
#pragma unroll
            for (int r = 0; r < 4; r++) acc[mt][nt][r] = 0.f;

    auto issue_stage = [&](int s, int k0) {
        const float* ga0 = A_HEAD ? A + head_idx(bm + aRow0, k0 + aC40)
                                  : A + (bm + aRow0) * C_DIM + k0 + aC40;
        const float* ga1 = A_HEAD ? A + head_idx(bm + aRow1, k0 + aC41)
                                  : A + (bm + aRow1) * C_DIM + k0 + aC41;
        CP_ASYNC16(asBase + s * asStageBytes + (aRow0 * AS_LD + aC40) * 4, ga0);
        CP_ASYNC16(asBase + s * asStageBytes + (aRow1 * AS_LD + aC41) * 4, ga1);
        const float* gb0 = W + (k0 + bRow0) * C_DIM + bn + bC40;
        const float* gb1 = W + (k0 + bRow1) * C_DIM + bn + bC41;
        CP_ASYNC16(bsBase + s * bsStageBytes + (bRow0 * BS_LD + bC40) * 4, gb0);
        CP_ASYNC16(bsBase + s * bsStageBytes + (bRow1 * BS_LD + bC41) * 4, gb1);
        CP_COMMIT();
    };

    issue_stage(0, 0);

    int stage = 0;
    for (int it = 0; it < C_DIM / BK; it++) {
        if (it + 1 < C_DIM / BK) {
            issue_stage(stage ^ 1, (it + 1) * BK);
            CP_WAIT(1);
        } else {
            CP_WAIT(0);
        }
        __syncthreads();

        const float* as = As[stage];
        const float* bs = Bs[stage];
#pragma unroll
        for (int kk = 0; kk < BK; kk += 8) {
            uint32_t ua[2][4];
#pragma unroll
            for (int mt = 0; mt < 2; mt++) {
                const float* ab = as + (wm + mt * 16 + group) * AS_LD + kk + tig;
                ua[mt][0] = f2tf32(ab[0]);
                ua[mt][1] = f2tf32(ab[8 * AS_LD]);
                ua[mt][2] = f2tf32(ab[4]);
                ua[mt][3] = f2tf32(ab[8 * AS_LD + 4]);
            }
#pragma unroll
            for (int nt = 0; nt < 8; nt++) {
                const float* bb = bs + (kk + tig) * BS_LD + wn + nt * 8 + group;
                const uint32_t ub0 = f2tf32(bb[0]);
                const uint32_t ub1 = f2tf32(bb[4 * BS_LD]);
                MMA_TF32(acc[0][nt][0], acc[0][nt][1], acc[0][nt][2], acc[0][nt][3],
                         ua[0][0], ua[0][1], ua[0][2], ua[0][3], ub0, ub1);
                MMA_TF32(acc[1][nt][0], acc[1][nt][1], acc[1][nt][2], acc[1][nt][3],
                         ua[1][0], ua[1][1], ua[1][2], ua[1][3], ub0, ub1);
            }
        }
        __syncthreads();
        stage ^= 1;
    }

    // Epilogue: c0/c1 at (row=group, col=2*tig), c2/c3 at row+8.
#pragma unroll
    for (int mt = 0; mt < 2; mt++) {
#pragma unroll
        for (int nt = 0; nt < 8; nt++) {
            const int n = bn + wn + nt * 8 + tig * 2;
            const float b0 = bias[n], b1 = bias[n + 1];
            const int m0 = bm + wm + mt * 16 + group;
            const int m1 = m0 + 8;
            float2 v0, v1;
            v0.x = acc[mt][nt][0] + b0; v0.y = acc[mt][nt][1] + b1;
            v1.x = acc[mt][nt][2] + b0; v1.y = acc[mt][nt][3] + b1;
            float* p0;
            float* p1;
            if (OUT_HEAD) { p0 = out + head_idx(m0, n); p1 = out + head_idx(m1, n); }
            else          { p0 = out + m0 * C_DIM + n;  p1 = out + m1 * C_DIM + n; }
            *(float2*)p0 = v0;
            *(float2*)p1 = v1;
        }
    }
}

// ---------------------------------------------------------------------------
// Flash attention (causal), fp32 SIMT (unchanged from R1).
// ---------------------------------------------------------------------------
#define QK_LD 65
#define PV_LD 64
#define SM_Q 0
#define SM_K (64 * QK_LD)
#define SM_V (2 * 64 * QK_LD)
#define SM_P (2 * 64 * QK_LD + 64 * PV_LD)
#define ATTN_SMEM_FLOATS (2 * 64 * QK_LD + 2 * 64 * PV_LD)

__global__ __launch_bounds__(256)
void attn_kernel(const float* __restrict__ Q, const float* __restrict__ K,
                 const float* __restrict__ V, float* __restrict__ Y)
{
    extern __shared__ float sm[];
    float* Qs = sm + SM_Q;
    float* Ks = sm + SM_K;
    float* Vs = sm + SM_V;
    float* Ps = sm + SM_P;

    const int bh = blockIdx.y;
    const int qb = blockIdx.x;
    const int q0 = qb << 6;
    const float* Qp = Q + (((size_t)bh << 11) + q0) * 64;
    const float* Kp = K + ((size_t)bh << 11) * 64;
    const float* Vp = V + ((size_t)bh << 11) * 64;

    const int tid = threadIdx.x;
    const int tx = tid & 15;
    const int ty = tid >> 4;
    const int r0 = ty << 2;
    const int c0 = tx << 2;

    for (int i = tid; i < 1024; i += 256) {
        const int r = i >> 4, c4 = (i & 15) << 2;
        const float4 v = *(const float4*)(Qp + (r << 6) + c4);
        float* dst = Qs + r * QK_LD + c4;
        dst[0] = v.x; dst[1] = v.y; dst[2] = v.z; dst[3] = v.w;
    }

    float o[4][4];
    float mi[4], li[4];
#pragma unroll
    for (int i = 0; i < 4; i++) {
        mi[i] = -1e30f; li[i] = 0.f;
#pragma unroll
        for (int j = 0; j < 4; j++) o[i][j] = 0.f;
    }

    for (int kt = 0; kt <= qb; kt++) {
        __syncthreads();
        const float* kbase = Kp + (kt << 12);
        const float* vbase = Vp + (kt << 12);
        for (int i = tid; i < 1024; i += 256) {
            const int r = i >> 4, c4 = (i & 15) << 2;
            const float4 kv = *(const float4*)(kbase + (r << 6) + c4);
            float* kd = Ks + r * QK_LD + c4;
            kd[0] = kv.x; kd[1] = kv.y; kd[2] = kv.z; kd[3] = kv.w;
            const float4 vv = *(const float4*)(vbase + (r << 6) + c4);
            *(float4*)(Vs + r * PV_LD + c4) = vv;
        }
        __syncthreads();

        float s[4][4];
#pragma unroll
        for (int i = 0; i < 4; i++)
#pragma unroll
            for (int j = 0; j < 4; j++) s[i][j] = 0.f;

        for (int d = 0; d < 64; d++) {
            float qa[4], kb[4];
#pragma unroll
            for (int i = 0; i < 4; i++) qa[i] = Qs[(r0 + i) * QK_LD + d];
#pragma unroll
            for (int j = 0; j < 4; j++) kb[j] = Ks[(c0 + j) * QK_LD + d];
#pragma unroll
            for (int i = 0; i < 4; i++)
#pragma unroll
                for (int j = 0; j < 4; j++)
                    s[i][j] += qa[i] * kb[j];
        }

        const bool diag = (kt == qb);
#pragma unroll
        for (int i = 0; i < 4; i++)
#pragma unroll
            for (int j = 0; j < 4; j++) {
                s[i][j] *= 0.125f;
                if (diag && (c0 + j) > (r0 + i)) s[i][j] = -1e30f;
            }

        float mnew[4], alpha[4];
#pragma unroll
        for (int i = 0; i < 4; i++) {
            float rm = fmaxf(fmaxf(s[i][0], s[i][1]), fmaxf(s[i][2], s[i][3]));
            rm = fmaxf(rm, __shfl_xor_sync(0xffffffffu, rm, 1, 16));
            rm = fmaxf(rm, __shfl_xor_sync(0xffffffffu, rm, 2, 16));
            rm = fmaxf(rm, __shfl_xor_sync(0xffffffffu, rm, 4, 16));
            rm = fmaxf(rm, __shfl_xor_sync(0xffffffffu, rm, 8, 16));
            mnew[i] = fmaxf(mi[i], rm);
            alpha[i] = __expf(mi[i] - mnew[i]);
        }
#pragma unroll
        for (int i = 0; i < 4; i++) {
            float4 pv;
            pv.x = __expf(s[i][0] - mnew[i]);
            pv.y = __expf(s[i][1] - mnew[i]);
            pv.z = __expf(s[i][2] - mnew[i]);
            pv.w = __expf(s[i][3] - mnew[i]);
            *(float4*)(Ps + (r0 + i) * PV_LD + c0) = pv;
            float sum = pv.x + pv.y + pv.z + pv.w;
            sum += __shfl_xor_sync(0xffffffffu, sum, 1, 16);
            sum += __shfl_xor_sync(0xffffffffu, sum, 2, 16);
            sum += __shfl_xor_sync(0xffffffffu, sum, 4, 16);
            sum += __shfl_xor_sync(0xffffffffu, sum, 8, 16);
            li[i] = li[i] * alpha[i] + sum;
            mi[i] = mnew[i];
#pragma unroll
            for (int j = 0; j < 4; j++) o[i][j] *= alpha[i];
        }
        __syncthreads();

        for (int c = 0; c < 64; c++) {
            float pa[4];
#pragma unroll
            for (int i = 0; i < 4; i++) pa[i] = Ps[(r0 + i) * PV_LD + c];
            const float4 vb = *(const float4*)(Vs + c * PV_LD + c0);
#pragma unroll
            for (int i = 0; i < 4; i++) {
                o[i][0] += pa[i] * vb.x;
                o[i][1] += pa[i] * vb.y;
                o[i][2] += pa[i] * vb.z;
                o[i][3] += pa[i] * vb.w;
            }
        }
    }

    float* yp = Y + (((size_t)bh << 11) + q0) * 64;
#pragma unroll
    for (int i = 0; i < 4; i++) {
        const float inv = 1.f / li[i];
        float4 v;
        v.x = o[i][0] * inv;
        v.y = o[i][1] * inv;
        v.z = o[i][2] * inv;
        v.w = o[i][3] * inv;
        *(float4*)(yp + (r0 + i) * 64 + c0) = v;
    }
}

// ---------------------------------------------------------------------------
extern "C" void kernel_launch(void* const* d_in, const int* in_sizes, int n_in,
                              void* d_out, int out_size)
{
    const float* x  = (const float*)d_in[0];
    const float* Wq = (const float*)d_in[1];
    const float* bq = (const float*)d_in[2];
    const float* Wk = (const float*)d_in[3];
    const float* bk = (const float*)d_in[4];
    const float* Wv = (const float*)d_in[5];
    const float* bv = (const float*)d_in[6];
    const float* Wp = (const float*)d_in[7];
    const float* bp = (const float*)d_in[8];
    float* out = (float*)d_out;

    float *q, *k, *v, *y;
    cudaGetSymbolAddress((void**)&q, g_q);
    cudaGetSymbolAddress((void**)&k, g_k);
    cudaGetSymbolAddress((void**)&v, g_v);
    cudaGetSymbolAddress((void**)&y, g_y);

    const dim3 gg(C_DIM / 128, M_ROWS / 128);   // (8, 64)
    gemm_tf32<false, true><<<gg, 256>>>(x, Wq, bq, q);
    gemm_tf32<false, true><<<gg, 256>>>(x, Wk, bk, k);
    gemm_tf32<false, true><<<gg, 256>>>(x, Wv, bv, v);

    const int attn_smem = ATTN_SMEM_FLOATS * (int)sizeof(float);  // 66048 B
    cudaFuncSetAttribute(attn_kernel, cudaFuncAttributeMaxDynamicSharedMemorySize,
                         attn_smem);
    const dim3 ga(T_LEN / 64, B_SZ * H_N);      // (32, 64)
    attn_kernel<<<ga, 256, attn_smem>>>(q, k, v, y);

    gemm_tf32<true, false><<<gg, 256>>>(y, Wp, bp, out);
}

// round 3
// speedup vs baseline: 2.9659x; 1.7674x over previous
#include <cuda_runtime.h>
#include <cstdint>

// Problem constants
#define B_SZ 4
#define T_LEN 2048
#define C_DIM 1024
#define H_N 16
#define D_H 64
#define M_ROWS 8192   // B*T

// Scratch: Q,K,V,Y in head layout [(b*H+h)*T + t]*D + d
__device__ float g_q[M_ROWS * C_DIM];
__device__ float g_k[M_ROWS * C_DIM];
__device__ float g_v[M_ROWS * C_DIM];
__device__ float g_y[M_ROWS * C_DIM];

__device__ __forceinline__ int head_idx(int m, int n) {
    return (((((m >> 11) << 4) + (n >> 6)) << 11 | (m & 2047)) << 6) + (n & 63);
}

__device__ __forceinline__ uint32_t f2tf32(float f) {
    uint32_t u;
    asm("cvt.rna.tf32.f32 %0, %1;" : "=r"(u) : "f"(f));
    return u;
}

#define MMA_TF32(C0,C1,C2,C3,A0,A1,A2,A3,B0,B1)                           \
    asm volatile("mma.sync.aligned.m16n8k8.row.col.f32.tf32.tf32.f32 "    \
        "{%0,%1,%2,%3},{%4,%5,%6,%7},{%8,%9},{%0,%1,%2,%3};"              \
        : "+f"(C0), "+f"(C1), "+f"(C2), "+f"(C3)                          \
        : "r"(A0), "r"(A1), "r"(A2), "r"(A3), "r"(B0), "r"(B1))

#define CP_ASYNC16(smem_u32, gptr)                                        \
    asm volatile("cp.async.ca.shared.global [%0], [%1], 16;"              \
        :: "r"(smem_u32), "l"(gptr))
#define CP_COMMIT()  asm volatile("cp.async.commit_group;")
#define CP_WAIT(N)   asm volatile("cp.async.wait_group %0;" :: "n"(N))

#define LOG2E_F 1.4426950408889634f

// 2^t on the FMA/ALU pipes (no MUFU). t <= ~0; clamp handles -inf masks.
__device__ __forceinline__ float exp2_fast(float t) {
    t = fmaxf(t, -115.0f);
    const float MAGIC = 12582912.0f;   // 2^23 + 2^22
    float zf = t + MAGIC;
    int n = __float_as_int(zf) - 0x4B400000;
    float r = t - (zf - MAGIC);        // r in [-0.5, 0.5]
    float p = 0.00133335581f;
    p = fmaf(p, r, 0.00961812911f);
    p = fmaf(p, r, 0.05550410866f);
    p = fmaf(p, r, 0.24022650696f);
    p = fmaf(p, r, 0.69314718056f);
    p = fmaf(p, r, 1.0f);
    return __int_as_float(__float_as_int(p) + (n << 23));
}

// ---------------------------------------------------------------------------
// TF32 tensor-core GEMM (unchanged from R2)
// ---------------------------------------------------------------------------
#define BK 16
#define AS_LD 20
#define BS_LD 132

template <bool A_HEAD, bool OUT_HEAD>
__global__ __launch_bounds__(256)
void gemm_tf32(const float* __restrict__ A, const float* __restrict__ W,
               const float* __restrict__ bias, float* __restrict__ out)
{
    __shared__ float As[2][128 * AS_LD];
    __shared__ float Bs[2][BK * BS_LD];

    const int bm = blockIdx.y * 128;
    const int bn = blockIdx.x * 128;
    const int tid = threadIdx.x;
    const int warp = tid >> 5;
    const int lane = tid & 31;
    const int group = lane >> 2;
    const int tig = lane & 3;
    const int wm = (warp >> 1) * 32;
    const int wn = (warp & 1) * 64;

    const int aRow0 = tid >> 2;
    const int aC40  = (tid & 3) << 2;
    const int aRow1 = (tid + 256) >> 2;
    const int aC41  = aC40;
    const int bRow0 = tid >> 5;
    const int bC40  = (tid & 31) << 2;
    const int bRow1 = (tid + 256) >> 5;
    const int bC41  = bC40;

    const uint32_t asBase = (uint32_t)__cvta_generic_to_shared(&As[0][0]);
    const uint32_t bsBase = (uint32_t)__cvta_generic_to_shared(&Bs[0][0]);
    const uint32_t asStageBytes = 128 * AS_LD * 4;
    const uint32_t bsStageBytes = BK * BS_LD * 4;

    float acc[2][8][4];
#pragma unroll
    for (int mt = 0; mt < 2; mt++)
#pragma unroll
        for (int nt = 0; nt < 8; nt++)
#pragma unroll
            for (int r = 0; r < 4; r++) acc[mt][nt][r] = 0.f;

    auto issue_stage = [&](int s, int k0) {
        const float* ga0 = A_HEAD ? A + head_idx(bm + aRow0, k0 + aC40)
                                  : A + (bm + aRow0) * C_DIM + k0 + aC40;
        const float* ga1 = A_HEAD ? A + head_idx(bm + aRow1, k0 + aC41)
                                  : A + (bm + aRow1) * C_DIM + k0 + aC41;
        CP_ASYNC16(asBase + s * asStageBytes + (aRow0 * AS_LD + aC40) * 4, ga0);
        CP_ASYNC16(asBase + s * asStageBytes + (aRow1 * AS_LD + aC41) * 4, ga1);
        const float* gb0 = W + (k0 + bRow0) * C_DIM + bn + bC40;
        const float* gb1 = W + (k0 + bRow1) * C_DIM + bn + bC41;
        CP_ASYNC16(bsBase + s * bsStageBytes + (bRow0 * BS_LD + bC40) * 4, gb0);
        CP_ASYNC16(bsBase + s * bsStageBytes + (bRow1 * BS_LD + bC41) * 4, gb1);
        CP_COMMIT();
    };

    issue_stage(0, 0);

    int stage = 0;
    for (int it = 0; it < C_DIM / BK; it++) {
        if (it + 1 < C_DIM / BK) {
            issue_stage(stage ^ 1, (it + 1) * BK);
            CP_WAIT(1);
        } else {
            CP_WAIT(0);
        }
        __syncthreads();

        const float* as = As[stage];
        const float* bs = Bs[stage];
#pragma unroll
        for (int kk = 0; kk < BK; kk += 8) {
            uint32_t ua[2][4];
#pragma unroll
            for (int mt = 0; mt < 2; mt++) {
                const float* ab = as + (wm + mt * 16 + group) * AS_LD + kk + tig;
                ua[mt][0] = f2tf32(ab[0]);
                ua[mt][1] = f2tf32(ab[8 * AS_LD]);
                ua[mt][2] = f2tf32(ab[4]);
                ua[mt][3] = f2tf32(ab[8 * AS_LD + 4]);
            }
#pragma unroll
            for (int nt = 0; nt < 8; nt++) {
                const float* bb = bs + (kk + tig) * BS_LD + wn + nt * 8 + group;
                const uint32_t ub0 = f2tf32(bb[0]);
                const uint32_t ub1 = f2tf32(bb[4 * BS_LD]);
                MMA_TF32(acc[0][nt][0], acc[0][nt][1], acc[0][nt][2], acc[0][nt][3],
                         ua[0][0], ua[0][1], ua[0][2], ua[0][3], ub0, ub1);
                MMA_TF32(acc[1][nt][0], acc[1][nt][1], acc[1][nt][2], acc[1][nt][3],
                         ua[1][0], ua[1][1], ua[1][2], ua[1][3], ub0, ub1);
            }
        }
        __syncthreads();
        stage ^= 1;
    }

#pragma unroll
    for (int mt = 0; mt < 2; mt++) {
#pragma unroll
        for (int nt = 0; nt < 8; nt++) {
            const int n = bn + wn + nt * 8 + tig * 2;
            const float b0 = bias[n], b1 = bias[n + 1];
            const int m0 = bm + wm + mt * 16 + group;
            const int m1 = m0 + 8;
            float2 v0, v1;
            v0.x = acc[mt][nt][0] + b0; v0.y = acc[mt][nt][1] + b1;
            v1.x = acc[mt][nt][2] + b0; v1.y = acc[mt][nt][3] + b1;
            float* p0;
            float* p1;
            if (OUT_HEAD) { p0 = out + head_idx(m0, n); p1 = out + head_idx(m1, n); }
            else          { p0 = out + m0 * C_DIM + n;  p1 = out + m1 * C_DIM + n; }
            *(float2*)p0 = v0;
            *(float2*)p1 = v1;
        }
    }
}

// ---------------------------------------------------------------------------
// Flash attention, tf32 tensor cores + FMA-pipe exp.
// Block = 128 threads (4 warps), Br=Bc=64, D=64. Warp w owns rows [16w,16w+16).
// Smem (tf32 u32): Qs/Ks/Ps stride 68, Vs stride 72 (bank-conflict-free frags).
// ---------------------------------------------------------------------------
#define ALD 68
#define VLD 72
#define OFF_Q 0
#define OFF_K (64 * ALD)
#define OFF_V (2 * 64 * ALD)
#define OFF_P (2 * 64 * ALD + 64 * VLD)
#define ATTN_U32 (3 * 64 * ALD + 64 * VLD)   // 17664 u32 = 70656 B

__global__ __launch_bounds__(128)
void attn_tc(const float* __restrict__ Q, const float* __restrict__ K,
             const float* __restrict__ V, float* __restrict__ Y)
{
    extern __shared__ uint32_t su[];
    uint32_t* Qs = su + OFF_Q;
    uint32_t* Ks = su + OFF_K;
    uint32_t* Vs = su + OFF_V;
    uint32_t* Ps = su + OFF_P;

    const int bh = blockIdx.y;
    const int qb = blockIdx.x;
    const int q0 = qb << 6;
    const float* Qp = Q + (((size_t)bh << 11) + q0) * 64;
    const float* Kp = K + ((size_t)bh << 11) * 64;
    const float* Vp = V + ((size_t)bh << 11) * 64;

    const int tid  = threadIdx.x;
    const int warp = tid >> 5;
    const int lane = tid & 31;
    const int g    = lane >> 2;    // 0..7
    const int t    = lane & 3;     // 0..3
    const int m0   = warp << 4;    // warp's row base

    // Load + convert Q
    for (int i = tid; i < 1024; i += 128) {
        const int r = i >> 4, c = (i & 15) << 2;
        const float4 v = *(const float4*)(Qp + (r << 6) + c);
        uint4 u;
        u.x = f2tf32(v.x); u.y = f2tf32(v.y); u.z = f2tf32(v.z); u.w = f2tf32(v.w);
        *(uint4*)&Qs[r * ALD + c] = u;
    }

    float oacc[8][4];
#pragma unroll
    for (int nf = 0; nf < 8; nf++)
#pragma unroll
        for (int r = 0; r < 4; r++) oacc[nf][r] = 0.f;
    float mrow0 = -1e30f, mrow1 = -1e30f, lrow0 = 0.f, lrow1 = 0.f;

    const float C1 = 0.125f * LOG2E_F;

    for (int kt = 0; kt <= qb; kt++) {
        __syncthreads();
        const float* kb = Kp + (kt << 12);
        const float* vb = Vp + (kt << 12);
        for (int i = tid; i < 1024; i += 128) {
            const int r = i >> 4, c = (i & 15) << 2;
            const float4 kv = *(const float4*)(kb + (r << 6) + c);
            uint4 ku;
            ku.x = f2tf32(kv.x); ku.y = f2tf32(kv.y); ku.z = f2tf32(kv.z); ku.w = f2tf32(kv.w);
            *(uint4*)&Ks[r * ALD + c] = ku;
            const float4 vv = *(const float4*)(vb + (r << 6) + c);
            uint4 vu;
            vu.x = f2tf32(vv.x); vu.y = f2tf32(vv.y); vu.z = f2tf32(vv.z); vu.w = f2tf32(vv.w);
            *(uint4*)&Vs[r * VLD + c] = vu;
        }
        __syncthreads();

        // S = Q K^T (raw, unscaled)
        float sacc[8][4];
#pragma unroll
        for (int nf = 0; nf < 8; nf++)
#pragma unroll
            for (int r = 0; r < 4; r++) sacc[nf][r] = 0.f;

#pragma unroll
        for (int kk8 = 0; kk8 < 8; kk8++) {
            const int kk = kk8 << 3;
            const uint32_t a0 = Qs[(m0 + g) * ALD + kk + t];
            const uint32_t a1 = Qs[(m0 + g + 8) * ALD + kk + t];
            const uint32_t a2 = Qs[(m0 + g) * ALD + kk + t + 4];
            const uint32_t a3 = Qs[(m0 + g + 8) * ALD + kk + t + 4];
#pragma unroll
            for (int nf = 0; nf < 8; nf++) {
                const uint32_t b0 = Ks[(nf * 8 + g) * ALD + kk + t];
                const uint32_t b1 = Ks[(nf * 8 + g) * ALD + kk + t + 4];
                MMA_TF32(sacc[nf][0], sacc[nf][1], sacc[nf][2], sacc[nf][3],
                         a0, a1, a2, a3, b0, b1);
            }
        }

        // causal mask (diagonal tile only); rows m0+g / m0+g+8, cols nf*8+2t{,+1}
        if (kt == qb) {
#pragma unroll
            for (int nf = 0; nf < 8; nf++) {
                const int c = nf * 8 + 2 * t;
                if (c     > m0 + g)     sacc[nf][0] = -1e30f;
                if (c + 1 > m0 + g)     sacc[nf][1] = -1e30f;
                if (c     > m0 + g + 8) sacc[nf][2] = -1e30f;
                if (c + 1 > m0 + g + 8) sacc[nf][3] = -1e30f;
            }
        }

        // row maxima (raw), reduce across the 4 lanes of each row group
        float mx0 = -1e30f, mx1 = -1e30f;
#pragma unroll
        for (int nf = 0; nf < 8; nf++) {
            mx0 = fmaxf(mx0, fmaxf(sacc[nf][0], sacc[nf][1]));
            mx1 = fmaxf(mx1, fmaxf(sacc[nf][2], sacc[nf][3]));
        }
        mx0 = fmaxf(mx0, __shfl_xor_sync(0xffffffffu, mx0, 1));
        mx0 = fmaxf(mx0, __shfl_xor_sync(0xffffffffu, mx0, 2));
        mx1 = fmaxf(mx1, __shfl_xor_sync(0xffffffffu, mx1, 1));
        mx1 = fmaxf(mx1, __shfl_xor_sync(0xffffffffu, mx1, 2));
        mx0 *= 0.125f; mx1 *= 0.125f;

        const float mn0 = fmaxf(mrow0, mx0);
        const float mn1 = fmaxf(mrow1, mx1);
        const float al0 = exp2_fast((mrow0 - mn0) * LOG2E_F);
        const float al1 = exp2_fast((mrow1 - mn1) * LOG2E_F);
        mrow0 = mn0; mrow1 = mn1;
        const float base0 = -mn0 * LOG2E_F;
        const float base1 = -mn1 * LOG2E_F;

        float sum0 = 0.f, sum1 = 0.f;
#pragma unroll
        for (int nf = 0; nf < 8; nf++) {
            const float p0 = exp2_fast(fmaf(sacc[nf][0], C1, base0));
            const float p1 = exp2_fast(fmaf(sacc[nf][1], C1, base0));
            const float p2 = exp2_fast(fmaf(sacc[nf][2], C1, base1));
            const float p3 = exp2_fast(fmaf(sacc[nf][3], C1, base1));
            sum0 += p0 + p1;
            sum1 += p2 + p3;
            uint2 u01; u01.x = f2tf32(p0); u01.y = f2tf32(p1);
            uint2 u23; u23.x = f2tf32(p2); u23.y = f2tf32(p3);
            *(uint2*)&Ps[(m0 + g) * ALD + nf * 8 + 2 * t] = u01;
            *(uint2*)&Ps[(m0 + g + 8) * ALD + nf * 8 + 2 * t] = u23;
            oacc[nf][0] *= al0; oacc[nf][1] *= al0;
            oacc[nf][2] *= al1; oacc[nf][3] *= al1;
        }
        sum0 += __shfl_xor_sync(0xffffffffu, sum0, 1);
        sum0 += __shfl_xor_sync(0xffffffffu, sum0, 2);
        sum1 += __shfl_xor_sync(0xffffffffu, sum1, 1);
        sum1 += __shfl_xor_sync(0xffffffffu, sum1, 2);
        lrow0 = lrow0 * al0 + sum0;
        lrow1 = lrow1 * al1 + sum1;

        __syncwarp();

        // O += P V
#pragma unroll
        for (int kk8 = 0; kk8 < 8; kk8++) {
            const int kk = kk8 << 3;
            const uint32_t pa0 = Ps[(m0 + g) * ALD + kk + t];
            const uint32_t pa1 = Ps[(m0 + g + 8) * ALD + kk + t];
            const uint32_t pa2 = Ps[(m0 + g) * ALD + kk + t + 4];
            const uint32_t pa3 = Ps[(m0 + g + 8) * ALD + kk + t + 4];
#pragma unroll
            for (int nf = 0; nf < 8; nf++) {
                const uint32_t vb0 = Vs[(kk + t) * VLD + nf * 8 + g];
                const uint32_t vb1 = Vs[(kk + t + 4) * VLD + nf * 8 + g];
                MMA_TF32(oacc[nf][0], oacc[nf][1], oacc[nf][2], oacc[nf][3],
                         pa0, pa1, pa2, pa3, vb0, vb1);
            }
        }
    }

    // normalize + store
    const float inv0 = 1.f / lrow0;
    const float inv1 = 1.f / lrow1;
    float* yp = Y + (((size_t)bh << 11) + q0) * 64;
#pragma unroll
    for (int nf = 0; nf < 8; nf++) {
        const int c = nf * 8 + 2 * t;
        float2 v0, v1;
        v0.x = oacc[nf][0] * inv0; v0.y = oacc[nf][1] * inv0;
        v1.x = oacc[nf][2] * inv1; v1.y = oacc[nf][3] * inv1;
        *(float2*)&yp[(m0 + g) * 64 + c] = v0;
        *(float2*)&yp[(m0 + g + 8) * 64 + c] = v1;
    }
}

// ---------------------------------------------------------------------------
extern "C" void kernel_launch(void* const* d_in, const int* in_sizes, int n_in,
                              void* d_out, int out_size)
{
    const float* x  = (const float*)d_in[0];
    const float* Wq = (const float*)d_in[1];
    const float* bq = (const float*)d_in[2];
    const float* Wk = (const float*)d_in[3];
    const float* bk = (const float*)d_in[4];
    const float* Wv = (const float*)d_in[5];
    const float* bv = (const float*)d_in[6];
    const float* Wp = (const float*)d_in[7];
    const float* bp = (const float*)d_in[8];
    float* out = (float*)d_out;

    float *q, *k, *v, *y;
    cudaGetSymbolAddress((void**)&q, g_q);
    cudaGetSymbolAddress((void**)&k, g_k);
    cudaGetSymbolAddress((void**)&v, g_v);
    cudaGetSymbolAddress((void**)&y, g_y);

    const dim3 gg(C_DIM / 128, M_ROWS / 128);   // (8, 64)
    gemm_tf32<false, true><<<gg, 256>>>(x, Wq, bq, q);
    gemm_tf32<false, true><<<gg, 256>>>(x, Wk, bk, k);
    gemm_tf32<false, true><<<gg, 256>>>(x, Wv, bv, v);

    const int attn_smem = ATTN_U32 * (int)sizeof(uint32_t);  // 70656 B
    cudaFuncSetAttribute(attn_tc, cudaFuncAttributeMaxDynamicSharedMemorySize,
                         attn_smem);
    const dim3 ga(T_LEN / 64, B_SZ * H_N);      // (32, 64)
    attn_tc<<<ga, 128, attn_smem>>>(q, k, v, y);

    gemm_tf32<true, false><<<gg, 256>>>(y, Wp, bp, out);
}